// round 3
// baseline (speedup 1.0000x reference)
#include <cuda_runtime.h>
#include <cstdint>
#include <math.h>

#define S_LEN   4096
#define DMODEL  768
#define NH      12
#define DH      64
#define QKV_LD  2304   // 3 * DMODEL

#define NEG_INF (__int_as_float(0xff800000))

// Scratch (allocation-free rule: __device__ globals)
__device__ float g_qkv[(size_t)S_LEN * QKV_LD];    // [4096, 2304]
__device__ float g_attn[(size_t)S_LEN * DMODEL];   // [4096, 768]

// ---------------------------------------------------------------------------
// Generic C[M,N] = A[M,K] @ B[N,K]^T + bias[N]   (fp32, 64x64 tile, 4x4/thread)
// ---------------------------------------------------------------------------
__global__ __launch_bounds__(256) void gemm_tn_bias(
    const float* __restrict__ A, const float* __restrict__ B,
    const float* __restrict__ bias, float* __restrict__ C,
    int M, int N, int K)
{
    __shared__ __align__(16) float As[16][64];
    __shared__ __align__(16) float Bs[16][64];

    const int t  = threadIdx.x;
    const int tx = t & 15, ty = t >> 4;   // 16x16 thread grid
    const int lr = t >> 2, lc = t & 3;    // loader: row 0..63, 4-float chunk 0..3
    const int m0 = blockIdx.y * 64, n0 = blockIdx.x * 64;

    const float* Ap = A + (size_t)(m0 + lr) * K + lc * 4;
    const float* Bp = B + (size_t)(n0 + lr) * K + lc * 4;

    float acc[4][4] = {};

    for (int k0 = 0; k0 < K; k0 += 16) {
        float4 av = *(const float4*)(Ap + k0);
        float4 bv = *(const float4*)(Bp + k0);
        As[lc*4+0][lr] = av.x; As[lc*4+1][lr] = av.y;
        As[lc*4+2][lr] = av.z; As[lc*4+3][lr] = av.w;
        Bs[lc*4+0][lr] = bv.x; Bs[lc*4+1][lr] = bv.y;
        Bs[lc*4+2][lr] = bv.z; Bs[lc*4+3][lr] = bv.w;
        __syncthreads();
#pragma unroll
        for (int kk = 0; kk < 16; kk++) {
            float4 a4 = *(const float4*)&As[kk][ty*4];
            float4 b4 = *(const float4*)&Bs[kk][tx*4];
            float aa[4] = {a4.x, a4.y, a4.z, a4.w};
            float bb[4] = {b4.x, b4.y, b4.z, b4.w};
#pragma unroll
            for (int i = 0; i < 4; i++)
#pragma unroll
                for (int j = 0; j < 4; j++)
                    acc[i][j] = fmaf(aa[i], bb[j], acc[i][j]);
        }
        __syncthreads();
    }

#pragma unroll
    for (int i = 0; i < 4; i++)
#pragma unroll
        for (int j = 0; j < 4; j++)
            C[(size_t)(m0 + ty*4 + i) * N + n0 + tx*4 + j] =
                acc[i][j] + bias[n0 + tx*4 + j];
}

// ---------------------------------------------------------------------------
// Causal flash attention, fp32. One CTA = (head, 64-row q tile). 256 threads.
// qkv layout: [S, 2304] with Q at col 0, K at col 768, V at col 1536,
// head h occupying cols h*64..h*64+63 of each segment.
// ---------------------------------------------------------------------------
#define APD 68   // padded row stride (floats) in smem tiles

__global__ __launch_bounds__(256) void attn_kernel(
    const float* __restrict__ qkv, float* __restrict__ out)
{
    const int qb = 63 - blockIdx.x;     // heavy tiles first (less tail)
    const int h  = blockIdx.y;
    const int t  = threadIdx.x;
    const int tx = t & 15, ty = t >> 4;
    const int lr = t >> 2, lc = t & 3;
    const int q0 = qb * 64;

    extern __shared__ __align__(16) float sm[];
    float* Qs = sm;                 // [d][r] transposed, stride APD
    float* Ks = sm + 64 * APD;      // [d][r] transposed
    float* Vs = sm + 2 * 64 * APD;  // [r][d] natural
    float* Ps = sm + 3 * 64 * APD;  // [k][q] transposed

    // Load Q tile (transposed into smem)
    {
        const float* p = qkv + (size_t)(q0 + lr) * QKV_LD + h * DH + lc * 16;
#pragma unroll
        for (int k = 0; k < 4; k++) {
            float4 v = *(const float4*)(p + k * 4);
            int d = lc * 16 + k * 4;
            Qs[(d+0)*APD + lr] = v.x;  Qs[(d+1)*APD + lr] = v.y;
            Qs[(d+2)*APD + lr] = v.z;  Qs[(d+3)*APD + lr] = v.w;
        }
    }

    float m_i[4], l_i[4], acc[4][4];
#pragma unroll
    for (int i = 0; i < 4; i++) {
        m_i[i] = NEG_INF; l_i[i] = 0.f;
#pragma unroll
        for (int j = 0; j < 4; j++) acc[i][j] = 0.f;
    }
    const float scale = 0.125f;  // 1/sqrt(64)

    for (int jb = 0; jb <= qb; jb++) {
        const int k0 = jb * 64;
        __syncthreads();  // previous iter's reads of Ks/Vs/Ps done; Qs ready
        // Load K tile (transposed) and V tile (natural)
        {
            const float* pk = qkv + (size_t)(k0 + lr) * QKV_LD + DMODEL     + h * DH + lc * 16;
            const float* pv = qkv + (size_t)(k0 + lr) * QKV_LD + 2*DMODEL   + h * DH + lc * 16;
#pragma unroll
            for (int k = 0; k < 4; k++) {
                float4 v = *(const float4*)(pk + k * 4);
                int d = lc * 16 + k * 4;
                Ks[(d+0)*APD + lr] = v.x;  Ks[(d+1)*APD + lr] = v.y;
                Ks[(d+2)*APD + lr] = v.z;  Ks[(d+3)*APD + lr] = v.w;
                float4 w = *(const float4*)(pv + k * 4);
                *(float4*)&Vs[lr * APD + lc * 16 + k * 4] = w;
            }
        }
        __syncthreads();

        // S = Q @ K^T (4x4 per thread)
        float s[4][4] = {};
#pragma unroll
        for (int d = 0; d < 64; d++) {
            float4 a4 = *(const float4*)&Qs[d*APD + ty*4];
            float4 b4 = *(const float4*)&Ks[d*APD + tx*4];
            float aa[4] = {a4.x, a4.y, a4.z, a4.w};
            float bb[4] = {b4.x, b4.y, b4.z, b4.w};
#pragma unroll
            for (int i = 0; i < 4; i++)
#pragma unroll
                for (int j = 0; j < 4; j++)
                    s[i][j] = fmaf(aa[i], bb[j], s[i][j]);
        }

        // scale + causal mask (only diagonal tile needs masking)
        const bool diag = (jb == qb);
#pragma unroll
        for (int i = 0; i < 4; i++)
#pragma unroll
            for (int j = 0; j < 4; j++) {
                float v = s[i][j] * scale;
                if (diag && (tx*4 + j > ty*4 + i)) v = NEG_INF;
                s[i][j] = v;
            }

        // row max over 64 cols (16 threads per row share ty; half-warp shuffle)
        float rm[4];
#pragma unroll
        for (int i = 0; i < 4; i++)
            rm[i] = fmaxf(fmaxf(s[i][0], s[i][1]), fmaxf(s[i][2], s[i][3]));
#pragma unroll
        for (int off = 8; off >= 1; off >>= 1)
#pragma unroll
            for (int i = 0; i < 4; i++)
                rm[i] = fmaxf(rm[i], __shfl_xor_sync(0xffffffffu, rm[i], off, 16));

        float alpha[4], rs[4];
#pragma unroll
        for (int i = 0; i < 4; i++) {
            float mn = fmaxf(m_i[i], rm[i]);
            alpha[i] = __expf(m_i[i] - mn);
            m_i[i] = mn;
            rs[i] = 0.f;
#pragma unroll
            for (int j = 0; j < 4; j++) {
                float p = __expf(s[i][j] - mn);
                s[i][j] = p;
                rs[i] += p;
            }
        }
#pragma unroll
        for (int off = 8; off >= 1; off >>= 1)
#pragma unroll
            for (int i = 0; i < 4; i++)
                rs[i] += __shfl_xor_sync(0xffffffffu, rs[i], off, 16);
#pragma unroll
        for (int i = 0; i < 4; i++) {
            l_i[i] = l_i[i] * alpha[i] + rs[i];
#pragma unroll
            for (int j = 0; j < 4; j++) acc[i][j] *= alpha[i];
        }

        // write P transposed [k][q]
#pragma unroll
        for (int i = 0; i < 4; i++)
#pragma unroll
            for (int j = 0; j < 4; j++)
                Ps[(tx*4 + j)*APD + ty*4 + i] = s[i][j];
        __syncthreads();

        // O += P @ V
#pragma unroll 16
        for (int kk = 0; kk < 64; kk++) {
            float4 a4 = *(const float4*)&Ps[kk*APD + ty*4];
            float4 b4 = *(const float4*)&Vs[kk*APD + tx*4];
            float aa[4] = {a4.x, a4.y, a4.z, a4.w};
            float bb[4] = {b4.x, b4.y, b4.z, b4.w};
#pragma unroll
            for (int i = 0; i < 4; i++)
#pragma unroll
                for (int j = 0; j < 4; j++)
                    acc[i][j] = fmaf(aa[i], bb[j], acc[i][j]);
        }
    }

    // normalize and store: out[s, h*64 + d]
#pragma unroll
    for (int i = 0; i < 4; i++) {
        float inv = 1.0f / l_i[i];
#pragma unroll
        for (int j = 0; j < 4; j++)
            out[(size_t)(q0 + ty*4 + i) * DMODEL + h * DH + tx*4 + j] =
                acc[i][j] * inv;
    }
}

// ---------------------------------------------------------------------------
extern "C" void kernel_launch(void* const* d_in, const int* in_sizes, int n_in,
                              void* d_out, int out_size)
{
    const float* x     = (const float*)d_in[0];
    const float* w_in  = (const float*)d_in[1];
    const float* b_in  = (const float*)d_in[2];
    const float* w_out = (const float*)d_in[3];
    const float* b_out = (const float*)d_in[4];
    float* out = (float*)d_out;

    float *qkv = nullptr, *attn = nullptr;
    cudaGetSymbolAddress((void**)&qkv,  g_qkv);
    cudaGetSymbolAddress((void**)&attn, g_attn);

    const int attn_smem = 4 * 64 * APD * (int)sizeof(float);  // 69632 B
    cudaFuncSetAttribute(attn_kernel,
                         cudaFuncAttributeMaxDynamicSharedMemorySize, attn_smem);

    dim3 blk(256);
    // QKV projection: [4096,768] @ [2304,768]^T
    gemm_tn_bias<<<dim3(QKV_LD/64, S_LEN/64), blk>>>(x, w_in, b_in, qkv,
                                                     S_LEN, QKV_LD, DMODEL);
    // Causal attention
    attn_kernel<<<dim3(S_LEN/64, NH), blk, attn_smem>>>(qkv, attn);
    // Output projection: [4096,768] @ [768,768]^T -> d_out
    gemm_tn_bias<<<dim3(DMODEL/64, S_LEN/64), blk>>>(attn, w_out, b_out, out,
                                                     S_LEN, DMODEL, DMODEL);
}

// round 4
// speedup vs baseline: 3.2870x; 3.2870x over previous
#include <cuda_runtime.h>
#include <cstdint>
#include <math.h>

#define S_LEN   4096
#define DMODEL  768
#define NH      12
#define DH      64
#define QKV_LD  2304   // 3 * DMODEL

#define NEG_INF (__int_as_float(0xff800000))

// Scratch (allocation-free rule: __device__ globals)
__device__ float g_qkv[(size_t)S_LEN * QKV_LD];    // [4096, 2304]
__device__ float g_attn[(size_t)S_LEN * DMODEL];   // [4096, 768]

// ---------------------------------------------------------------------------
// tf32 helpers (warp-level mma.sync m16n8k8)
// ---------------------------------------------------------------------------
__device__ __forceinline__ uint32_t f2tf32(float f) {
    uint32_t r;
    asm("cvt.rna.tf32.f32 %0, %1;" : "=r"(r) : "f"(f));
    return r;
}

__device__ __forceinline__ void mma_tf32(float* d, const uint32_t* a, const uint32_t* b) {
    asm volatile(
        "mma.sync.aligned.m16n8k8.row.col.f32.tf32.tf32.f32 "
        "{%0,%1,%2,%3}, {%4,%5,%6,%7}, {%8,%9}, {%0,%1,%2,%3};"
        : "+f"(d[0]), "+f"(d[1]), "+f"(d[2]), "+f"(d[3])
        : "r"(a[0]), "r"(a[1]), "r"(a[2]), "r"(a[3]), "r"(b[0]), "r"(b[1]));
}

// ---------------------------------------------------------------------------
// C[M,N] = A[M,K] @ B[N,K]^T + bias[N]   tf32 tensor-core GEMM
// CTA tile 128x128, 8 warps (2x4), warp tile 64x32, K-step 32, double buffer.
// smem stride 36 (== 4 mod 32) -> conflict-free fragment loads.
// ---------------------------------------------------------------------------
#define GSTR 36

__global__ __launch_bounds__(256) void gemm_tf32(
    const float* __restrict__ A, const float* __restrict__ B,
    const float* __restrict__ bias, float* __restrict__ C,
    int M, int N, int K)
{
    extern __shared__ uint32_t smg[];
    uint32_t* As = smg;                   // [2][128*GSTR]
    uint32_t* Bs = smg + 2 * 128 * GSTR;  // [2][128*GSTR]

    const int t = threadIdx.x, lane = t & 31;
    const int w = t >> 5, wm = w >> 2, wn = w & 3;
    const int g = lane >> 2, tg = lane & 3;
    const int m0 = blockIdx.y * 128, n0 = blockIdx.x * 128;
    const int KT = K >> 5;

    float acc[4][4][4] = {};
    float4 ra[4], rb[4];

    // prologue: load k-tile 0
#pragma unroll
    for (int i = 0; i < 4; i++) {
        int s = t + i * 256, row = s >> 3, c = (s & 7) * 4;
        ra[i] = *(const float4*)&A[(size_t)(m0 + row) * K + c];
        rb[i] = *(const float4*)&B[(size_t)(n0 + row) * K + c];
    }
#pragma unroll
    for (int i = 0; i < 4; i++) {
        int s = t + i * 256, row = s >> 3, c = (s & 7) * 4;
        *(uint4*)&As[row * GSTR + c] =
            make_uint4(f2tf32(ra[i].x), f2tf32(ra[i].y), f2tf32(ra[i].z), f2tf32(ra[i].w));
        *(uint4*)&Bs[row * GSTR + c] =
            make_uint4(f2tf32(rb[i].x), f2tf32(rb[i].y), f2tf32(rb[i].z), f2tf32(rb[i].w));
    }
    __syncthreads();

    for (int kt = 0; kt < KT; kt++) {
        if (kt + 1 < KT) {
#pragma unroll
            for (int i = 0; i < 4; i++) {
                int s = t + i * 256, row = s >> 3, c = (s & 7) * 4;
                ra[i] = *(const float4*)&A[(size_t)(m0 + row) * K + (kt + 1) * 32 + c];
                rb[i] = *(const float4*)&B[(size_t)(n0 + row) * K + (kt + 1) * 32 + c];
            }
        }
        const uint32_t* ab = As + (kt & 1) * 128 * GSTR;
        const uint32_t* bb = Bs + (kt & 1) * 128 * GSTR;
#pragma unroll
        for (int kk = 0; kk < 4; kk++) {
            uint32_t afr[4][4], bfr[4][2];
#pragma unroll
            for (int mt = 0; mt < 4; mt++) {
                int r = wm * 64 + mt * 16 + g;
                afr[mt][0] = ab[r * GSTR + kk * 8 + tg];
                afr[mt][1] = ab[(r + 8) * GSTR + kk * 8 + tg];
                afr[mt][2] = ab[r * GSTR + kk * 8 + tg + 4];
                afr[mt][3] = ab[(r + 8) * GSTR + kk * 8 + tg + 4];
            }
#pragma unroll
            for (int nt = 0; nt < 4; nt++) {
                int c = wn * 32 + nt * 8 + g;
                bfr[nt][0] = bb[c * GSTR + kk * 8 + tg];
                bfr[nt][1] = bb[c * GSTR + kk * 8 + tg + 4];
            }
#pragma unroll
            for (int mt = 0; mt < 4; mt++)
#pragma unroll
                for (int nt = 0; nt < 4; nt++)
                    mma_tf32(acc[mt][nt], afr[mt], bfr[nt]);
        }
        if (kt + 1 < KT) {
            uint32_t* an = As + ((kt + 1) & 1) * 128 * GSTR;
            uint32_t* bn = Bs + ((kt + 1) & 1) * 128 * GSTR;
#pragma unroll
            for (int i = 0; i < 4; i++) {
                int s = t + i * 256, row = s >> 3, c = (s & 7) * 4;
                *(uint4*)&an[row * GSTR + c] =
                    make_uint4(f2tf32(ra[i].x), f2tf32(ra[i].y), f2tf32(ra[i].z), f2tf32(ra[i].w));
                *(uint4*)&bn[row * GSTR + c] =
                    make_uint4(f2tf32(rb[i].x), f2tf32(rb[i].y), f2tf32(rb[i].z), f2tf32(rb[i].w));
            }
        }
        __syncthreads();
    }

    // epilogue: bias + store (float2, 8B aligned since col even)
#pragma unroll
    for (int nt = 0; nt < 4; nt++) {
        int cb = n0 + wn * 32 + nt * 8 + 2 * tg;
        float2 bv = *(const float2*)&bias[cb];
#pragma unroll
        for (int mt = 0; mt < 4; mt++) {
            int r = m0 + wm * 64 + mt * 16 + g;
            *(float2*)&C[(size_t)r * N + cb] =
                make_float2(acc[mt][nt][0] + bv.x, acc[mt][nt][1] + bv.y);
            *(float2*)&C[(size_t)(r + 8) * N + cb] =
                make_float2(acc[mt][nt][2] + bv.x, acc[mt][nt][3] + bv.y);
        }
    }
}

// ---------------------------------------------------------------------------
// Causal flash attention, tf32 tensor cores.
// One CTA = (head, 128-row q tile). 8 warps, each owns 16 q rows (one m16).
// Bc = 64. S/P/O live in m16n8 fragments; P round-trips through smem.
// ---------------------------------------------------------------------------
__global__ __launch_bounds__(256) void attn_tf32(
    const float* __restrict__ qkv, float* __restrict__ out)
{
    extern __shared__ uint32_t sma[];
    uint32_t* Qs = sma;              // [128][68]
    uint32_t* Ps = Qs + 128 * 68;    // [128][68]
    uint32_t* Ks = Ps + 128 * 68;    // [64][68]
    uint32_t* Vs = Ks + 64 * 68;     // [64][72]

    const int qb = (int)(gridDim.x - 1) - (int)blockIdx.x;  // heavy tiles first
    const int h = blockIdx.y;
    const int q0 = qb * 128;
    const int t = threadIdx.x, lane = t & 31, w = t >> 5;
    const int g = lane >> 2, tg = lane & 3;
    const int rb = w * 16;

    // Load Q tile (tf32) — 128x64
#pragma unroll
    for (int i = 0; i < 8; i++) {
        int s = t + i * 256, row = s >> 4, c = (s & 15) * 4;
        float4 v = *(const float4*)&qkv[(size_t)(q0 + row) * QKV_LD + h * DH + c];
        *(uint4*)&Qs[row * 68 + c] =
            make_uint4(f2tf32(v.x), f2tf32(v.y), f2tf32(v.z), f2tf32(v.w));
    }

    float o[8][4] = {};
    float m0r = NEG_INF, m1r = NEG_INF;
    float l0r = 0.f, l1r = 0.f;
    const float sc = 0.125f;  // 1/sqrt(64)

    const int jbmax = 2 * qb + 1;
    for (int jb = 0; jb <= jbmax; jb++) {
        __syncthreads();  // all warps done reading K/V of prev iter
        // Load K,V tiles (64x64 each)
#pragma unroll
        for (int i = 0; i < 4; i++) {
            int s = t + i * 256, row = s >> 4, c = (s & 15) * 4;
            const float* bp = &qkv[(size_t)(jb * 64 + row) * QKV_LD + h * DH + c];
            float4 kv = *(const float4*)(bp + DMODEL);
            float4 vv = *(const float4*)(bp + 2 * DMODEL);
            *(uint4*)&Ks[row * 68 + c] =
                make_uint4(f2tf32(kv.x), f2tf32(kv.y), f2tf32(kv.z), f2tf32(kv.w));
            *(uint4*)&Vs[row * 72 + c] =
                make_uint4(f2tf32(vv.x), f2tf32(vv.y), f2tf32(vv.z), f2tf32(vv.w));
        }
        __syncthreads();

        // warps entirely above the diagonal skip this k-tile
        if (jb * 64 > q0 + rb + 15) continue;

        // S = Q @ K^T  (per warp: m16 x n64, contraction 64)
        float sf[8][4] = {};
#pragma unroll
        for (int d8 = 0; d8 < 8; d8++) {
            uint32_t a[4];
            a[0] = Qs[(rb + g) * 68 + d8 * 8 + tg];
            a[1] = Qs[(rb + g + 8) * 68 + d8 * 8 + tg];
            a[2] = Qs[(rb + g) * 68 + d8 * 8 + tg + 4];
            a[3] = Qs[(rb + g + 8) * 68 + d8 * 8 + tg + 4];
#pragma unroll
            for (int nt = 0; nt < 8; nt++) {
                uint32_t b[2];
                b[0] = Ks[(nt * 8 + g) * 68 + d8 * 8 + tg];
                b[1] = Ks[(nt * 8 + g) * 68 + d8 * 8 + tg + 4];
                mma_tf32(sf[nt], a, b);
            }
        }

        // scale + causal mask (col > row -> -inf; exact for all tiles)
        const int row0 = q0 + rb + g;
#pragma unroll
        for (int nt = 0; nt < 8; nt++) {
            int c0 = jb * 64 + nt * 8 + 2 * tg;
            sf[nt][0] = (c0     > row0)     ? NEG_INF : sf[nt][0] * sc;
            sf[nt][1] = (c0 + 1 > row0)     ? NEG_INF : sf[nt][1] * sc;
            sf[nt][2] = (c0     > row0 + 8) ? NEG_INF : sf[nt][2] * sc;
            sf[nt][3] = (c0 + 1 > row0 + 8) ? NEG_INF : sf[nt][3] * sc;
        }

        // row max (2 rows per thread), quad reduction
        float mx0 = NEG_INF, mx1 = NEG_INF;
#pragma unroll
        for (int nt = 0; nt < 8; nt++) {
            mx0 = fmaxf(mx0, fmaxf(sf[nt][0], sf[nt][1]));
            mx1 = fmaxf(mx1, fmaxf(sf[nt][2], sf[nt][3]));
        }
        mx0 = fmaxf(mx0, __shfl_xor_sync(0xffffffffu, mx0, 1));
        mx0 = fmaxf(mx0, __shfl_xor_sync(0xffffffffu, mx0, 2));
        mx1 = fmaxf(mx1, __shfl_xor_sync(0xffffffffu, mx1, 1));
        mx1 = fmaxf(mx1, __shfl_xor_sync(0xffffffffu, mx1, 2));

        float mn0 = fmaxf(m0r, mx0), mn1 = fmaxf(m1r, mx1);
        float al0 = __expf(m0r - mn0), al1 = __expf(m1r - mn1);
        m0r = mn0; m1r = mn1;

        float s0 = 0.f, s1 = 0.f;
#pragma unroll
        for (int nt = 0; nt < 8; nt++) {
            float p0 = __expf(sf[nt][0] - mn0); sf[nt][0] = p0; s0 += p0;
            float p1 = __expf(sf[nt][1] - mn0); sf[nt][1] = p1; s0 += p1;
            float p2 = __expf(sf[nt][2] - mn1); sf[nt][2] = p2; s1 += p2;
            float p3 = __expf(sf[nt][3] - mn1); sf[nt][3] = p3; s1 += p3;
        }
        s0 += __shfl_xor_sync(0xffffffffu, s0, 1);
        s0 += __shfl_xor_sync(0xffffffffu, s0, 2);
        s1 += __shfl_xor_sync(0xffffffffu, s1, 1);
        s1 += __shfl_xor_sync(0xffffffffu, s1, 2);
        l0r = l0r * al0 + s0;
        l1r = l1r * al1 + s1;
#pragma unroll
        for (int nt = 0; nt < 8; nt++) {
            o[nt][0] *= al0; o[nt][1] *= al0;
            o[nt][2] *= al1; o[nt][3] *= al1;
        }

        // P -> smem (tf32); each warp only touches/reads its own 16 rows
#pragma unroll
        for (int nt = 0; nt < 8; nt++) {
            int b0 = (rb + g) * 68 + nt * 8 + 2 * tg;
            Ps[b0]     = f2tf32(sf[nt][0]);
            Ps[b0 + 1] = f2tf32(sf[nt][1]);
            int b1 = (rb + g + 8) * 68 + nt * 8 + 2 * tg;
            Ps[b1]     = f2tf32(sf[nt][2]);
            Ps[b1 + 1] = f2tf32(sf[nt][3]);
        }
        __syncwarp();

        // O += P @ V  (per warp: m16 x n64, contraction 64)
#pragma unroll
        for (int kk = 0; kk < 8; kk++) {
            uint32_t a[4];
            a[0] = Ps[(rb + g) * 68 + kk * 8 + tg];
            a[1] = Ps[(rb + g + 8) * 68 + kk * 8 + tg];
            a[2] = Ps[(rb + g) * 68 + kk * 8 + tg + 4];
            a[3] = Ps[(rb + g + 8) * 68 + kk * 8 + tg + 4];
#pragma unroll
            for (int nt = 0; nt < 8; nt++) {
                uint32_t b[2];
                b[0] = Vs[(kk * 8 + tg) * 72 + nt * 8 + g];
                b[1] = Vs[(kk * 8 + tg + 4) * 72 + nt * 8 + g];
                mma_tf32(o[nt], a, b);
            }
        }
    }

    // epilogue: normalize + store
    float inv0 = 1.0f / l0r, inv1 = 1.0f / l1r;
    const int r0 = q0 + rb + g;
#pragma unroll
    for (int nt = 0; nt < 8; nt++) {
        int cb = h * DH + nt * 8 + 2 * tg;
        *(float2*)&out[(size_t)r0 * DMODEL + cb] =
            make_float2(o[nt][0] * inv0, o[nt][1] * inv0);
        *(float2*)&out[(size_t)(r0 + 8) * DMODEL + cb] =
            make_float2(o[nt][2] * inv1, o[nt][3] * inv1);
    }
}

// ---------------------------------------------------------------------------
extern "C" void kernel_launch(void* const* d_in, const int* in_sizes, int n_in,
                              void* d_out, int out_size)
{
    const float* x     = (const float*)d_in[0];
    const float* w_in  = (const float*)d_in[1];
    const float* b_in  = (const float*)d_in[2];
    const float* w_out = (const float*)d_in[3];
    const float* b_out = (const float*)d_in[4];
    float* out = (float*)d_out;

    float *qkv = nullptr, *attn = nullptr;
    cudaGetSymbolAddress((void**)&qkv,  g_qkv);
    cudaGetSymbolAddress((void**)&attn, g_attn);

    const int gemm_smem = 4 * 128 * GSTR * (int)sizeof(uint32_t);       // 73728
    const int attn_smem = (2 * 128 * 68 + 64 * 68 + 64 * 72) * (int)sizeof(uint32_t); // 105472
    cudaFuncSetAttribute(gemm_tf32,
                         cudaFuncAttributeMaxDynamicSharedMemorySize, gemm_smem);
    cudaFuncSetAttribute(attn_tf32,
                         cudaFuncAttributeMaxDynamicSharedMemorySize, attn_smem);

    dim3 blk(256);
    // QKV projection: [4096,2304] = x @ w_in^T + b_in
    gemm_tf32<<<dim3(QKV_LD / 128, S_LEN / 128), blk, gemm_smem>>>(
        x, w_in, b_in, qkv, S_LEN, QKV_LD, DMODEL);
    // Causal attention
    attn_tf32<<<dim3(S_LEN / 128, NH), blk, attn_smem>>>(qkv, attn);
    // Output projection: [4096,768] -> d_out
    gemm_tf32<<<dim3(DMODEL / 128, S_LEN / 128), blk, gemm_smem>>>(
        attn, w_out, b_out, out, S_LEN, DMODEL, DMODEL);
}